// round 15
// baseline (speedup 1.0000x reference)
#include <cuda_runtime.h>
#include <cuda_fp16.h>
#include <cstdint>
#include <math.h>

typedef unsigned int u32;

// ---------------------------------------------------------------------------
// Problem constants
// ---------------------------------------------------------------------------
#define DIM     1024
#define NH      8
#define Q_C     128
#define Q_NOPE  96
#define Q_ROPE  32
#define KV_C    128
#define K_ROPE  64
#define K_NOPE  64
#define V_HD    256
#define S_LEN   2048
#define BATCH   2
#define BSROWS  (BATCH * S_LEN)       // 4096
#define QK_D    128
#define DQKV_N  (Q_C + KV_C + K_ROPE) // 320
#define EPSV    1e-8f
// 1/sqrt(128) * log2(e)  (softmax runs in base-2 domain)
#define QSC     (0.08838834764831845f * 1.4426950408889634f)

// ---------------------------------------------------------------------------
// Scratch (static device globals; no allocation allowed)
// ---------------------------------------------------------------------------
__device__ __half hx     [BSROWS * DIM];
__device__ __half hw_dqkv[DIM * DQKV_N];
__device__ __half hw_uq  [Q_C * (NH * QK_D)];
__device__ __half hw_ukv [KV_C * (NH * (K_NOPE + V_HD))];
__device__ __half hw_o   [(NH * V_HD) * DIM];

__device__ float  g_cq_raw[BSROWS * Q_C];
__device__ __half g_cq_h  [BSROWS * Q_C];
__device__ float  g_ckvkr [BSROWS * (KV_C + K_ROPE)];
__device__ __half g_ckv_h [BSROWS * KV_C];
__device__ __half g_qs    [BATCH * NH * S_LEN * QK_D];   // scaled+roped q
__device__ __half g_ks    [BATCH * NH * S_LEN * QK_D];
__device__ __half g_vs    [BATCH * NH * S_LEN * V_HD];
__device__ __half g_attn_h[BSROWS * (NH * V_HD)];

// ---------------------------------------------------------------------------
// PTX helpers
// ---------------------------------------------------------------------------
__device__ __forceinline__ u32 smem_a(const void* p) {
    return (u32)__cvta_generic_to_shared(p);
}
__device__ __forceinline__ void ldsm4(u32* r, u32 a) {
    asm volatile("ldmatrix.sync.aligned.m8n8.x4.shared.b16 {%0,%1,%2,%3},[%4];"
                 : "=r"(r[0]), "=r"(r[1]), "=r"(r[2]), "=r"(r[3]) : "r"(a));
}
__device__ __forceinline__ void ldsm4t(u32* r, u32 a) {
    asm volatile("ldmatrix.sync.aligned.m8n8.x4.trans.shared.b16 {%0,%1,%2,%3},[%4];"
                 : "=r"(r[0]), "=r"(r[1]), "=r"(r[2]), "=r"(r[3]) : "r"(a));
}
__device__ __forceinline__ void mma16816(float* d, const u32* a, const u32* b) {
    asm volatile("mma.sync.aligned.m16n8k16.row.col.f32.f16.f16.f32 "
                 "{%0,%1,%2,%3},{%4,%5,%6,%7},{%8,%9},{%0,%1,%2,%3};"
                 : "+f"(d[0]), "+f"(d[1]), "+f"(d[2]), "+f"(d[3])
                 : "r"(a[0]), "r"(a[1]), "r"(a[2]), "r"(a[3]), "r"(b[0]), "r"(b[1]));
}
__device__ __forceinline__ void cp_async16(u32 s, const void* g) {
    asm volatile("cp.async.cg.shared.global [%0], [%1], 16;" :: "r"(s), "l"(g));
}
__device__ __forceinline__ void cp_commit() {
    asm volatile("cp.async.commit_group;");
}
template <int N>
__device__ __forceinline__ void cp_wait() {
    asm volatile("cp.async.wait_group %0;" :: "n"(N));
}

// ---------------------------------------------------------------------------
// Merged fp32 -> fp16 conversion (one launch). dq/dkv interleave into hw_dqkv.
// ---------------------------------------------------------------------------
#define CN0 (BSROWS * DIM / 8)                         // x
#define CN1 (CN0 + DIM * Q_C / 8)                      // dq  -> hw_dqkv cols 0..127
#define CN2 (CN1 + DIM * (KV_C + K_ROPE) / 8)          // dkv -> hw_dqkv cols 128..319
#define CN3 (CN2 + Q_C * NH * QK_D / 8)                // uq
#define CN4 (CN3 + KV_C * NH * (K_NOPE + V_HD) / 8)    // ukv
#define CN5 (CN4 + NH * V_HD * DIM / 8)                // o

__global__ void cvt_all_k(const float* __restrict__ x,   const float* __restrict__ dq,
                          const float* __restrict__ uq,  const float* __restrict__ dkv,
                          const float* __restrict__ ukv, const float* __restrict__ o)
{
    int i = blockIdx.x * blockDim.x + threadIdx.x;
    if (i >= CN5) return;
    const float* src; __half* dstp; int off;
    if (i < CN0)      { src = x;   off = i;       dstp = hx + (size_t)off * 8; }
    else if (i < CN1) { src = dq;  off = i - CN0;
                        int r = off / 16, c = (off * 8) % Q_C;
                        dstp = hw_dqkv + (size_t)r * DQKV_N + c; }
    else if (i < CN2) { src = dkv; off = i - CN1;
                        int r = off / 24, c = (off * 8) % (KV_C + K_ROPE);
                        dstp = hw_dqkv + (size_t)r * DQKV_N + Q_C + c; }
    else if (i < CN3) { src = uq;  off = i - CN2; dstp = hw_uq  + (size_t)off * 8; }
    else if (i < CN4) { src = ukv; off = i - CN3; dstp = hw_ukv + (size_t)off * 8; }
    else              { src = o;   off = i - CN4; dstp = hw_o   + (size_t)off * 8; }
    float4 f0 = ((const float4*)src)[2 * off];
    float4 f1 = ((const float4*)src)[2 * off + 1];
    union { __half2 h[4]; int4 v; } u;
    u.h[0] = __floats2half2_rn(f0.x, f0.y);
    u.h[1] = __floats2half2_rn(f0.z, f0.w);
    u.h[2] = __floats2half2_rn(f1.x, f1.y);
    u.h[3] = __floats2half2_rn(f1.z, f1.w);
    *(int4*)dstp = u.v;
}

// ---------------------------------------------------------------------------
// HGEMM: 128x64x32 tile, 256 threads (8 warps 4x2), warp tile 32x32, fp16 mma.
// 3-stage cp.async pipeline. Coalesced epilogue via smem staging (EPI 1/3/4).
// EPI: 0=out fp32 direct, 1=fused dq+dkv (fp32), 3=Q scatter, 4=KV scatter
// ---------------------------------------------------------------------------
#define HBM 128
#define HBN 64
#define HBK 32
#define ALD 40
#define BLD 72
#define NSTG 3
#define A_STG (HBM * ALD)        // halfs per A stage
#define B_STG (HBK * BLD)        // halfs per B stage
#define SMEM_HG (NSTG * (A_STG + B_STG) * 2)   // 44544 bytes
#define FSTRIDE 68               // float staging row stride
#define HSTRIDE 72               // half staging row stride

template <int EPI, int ASRC>
__global__ void __launch_bounds__(256) hgemm_k(const float* __restrict__ bias,
                                               const float* __restrict__ bias2,
                                               float* __restrict__ C, int N, int K,
                                               const int* __restrict__ pos)
{
    const __half* A = ASRC == 0 ? hx : ASRC == 1 ? g_cq_h : ASRC == 2 ? g_ckv_h : g_attn_h;
    const __half* B = EPI == 1 ? hw_dqkv : EPI == 3 ? hw_uq :
                      EPI == 4 ? hw_ukv : hw_o;

    __shared__ __align__(16) char smem_raw[SMEM_HG];
    __half* sA = (__half*)smem_raw;                      // [NSTG][HBM][ALD]
    __half* sB = (__half*)smem_raw + NSTG * A_STG;       // [NSTG][HBK][BLD]

    int tid = threadIdx.x, warp = tid >> 5, lane = tid & 31;
    int m0 = blockIdx.y * HBM, n0 = blockIdx.x * HBN;
    int wm = (warp >> 1) * 32, wn = (warp & 1) * 32;

    float acc[2][4][4];
#pragma unroll
    for (int i = 0; i < 2; i++)
#pragma unroll
        for (int j = 0; j < 4; j++)
#pragma unroll
            for (int k = 0; k < 4; k++) acc[i][j][k] = 0.f;

    int ar = tid >> 2, ac = (tid & 3) * 8;
    int br = tid >> 3, bc = (tid & 7) * 8;
    u32 sA_a = smem_a(sA), sB_a = smem_a(sB);

    auto load_stage = [&](int st, int k0) {
        cp_async16(sA_a + (((size_t)st * HBM + ar) * ALD + ac) * 2,
                   &A[(size_t)(m0 + ar) * K + k0 + ac]);
        cp_async16(sA_a + (((size_t)st * HBM + 64 + ar) * ALD + ac) * 2,
                   &A[(size_t)(m0 + 64 + ar) * K + k0 + ac]);
        cp_async16(sB_a + (((size_t)st * HBK + br) * BLD + bc) * 2,
                   &B[(size_t)(k0 + br) * N + n0 + bc]);
        cp_commit();
    };

    int nIt = K / HBK;
    load_stage(0, 0);
    load_stage(1, HBK);
    for (int it = 0; it < nIt; it++) {
        cp_wait<1>();
        __syncthreads();
        if (it + 2 < nIt) load_stage((it + 2) % NSTG, (it + 2) * HBK);
        else cp_commit();   // keep group count advancing so wait<1> pins stage it
        int st = it % NSTG;
        const __half* sAb = sA + st * A_STG;
        const __half* sBb = sB + st * B_STG;
#pragma unroll
        for (int ks = 0; ks < 2; ks++) {
            u32 a[2][4], bm[4][2];
#pragma unroll
            for (int mi = 0; mi < 2; mi++)
                ldsm4(a[mi], smem_a(&sAb[(wm + mi * 16 + (lane & 15)) * ALD + ks * 16 + (lane >> 4) * 8]));
#pragma unroll
            for (int njp = 0; njp < 2; njp++) {
                u32 r[4];
                ldsm4t(r, smem_a(&sBb[(ks * 16 + ((lane >> 3) & 1) * 8 + (lane & 7)) * BLD
                                      + wn + njp * 16 + (lane >> 4) * 8]));
                bm[njp * 2][0] = r[0]; bm[njp * 2][1] = r[1];
                bm[njp * 2 + 1][0] = r[2]; bm[njp * 2 + 1][1] = r[3];
            }
#pragma unroll
            for (int mi = 0; mi < 2; mi++)
#pragma unroll
                for (int nj = 0; nj < 4; nj++)
                    mma16816(acc[mi][nj], a[mi], bm[nj]);
        }
    }

    // ------------------------- epilogue -------------------------
    if (EPI == 0) {
#pragma unroll
        for (int mi = 0; mi < 2; mi++)
#pragma unroll
            for (int nj = 0; nj < 4; nj++) {
                int row = m0 + wm + mi * 16 + (lane >> 2);
                int col = n0 + wn + nj * 8 + 2 * (lane & 3);
                float b0 = bias[col], b1 = bias[col + 1];
                *(float2*)&C[(size_t)row * N + col] =
                    make_float2(acc[mi][nj][0] + b0, acc[mi][nj][1] + b1);
                *(float2*)&C[(size_t)(row + 8) * N + col] =
                    make_float2(acc[mi][nj][2] + b0, acc[mi][nj][3] + b1);
            }
        return;
    }

    __syncthreads();   // done reading pipeline smem; reuse for staging

    if (EPI == 1) {
        float* st = (float*)smem_raw;   // [128][FSTRIDE]
#pragma unroll
        for (int mi = 0; mi < 2; mi++)
#pragma unroll
            for (int nj = 0; nj < 4; nj++) {
                int rl = wm + mi * 16 + (lane >> 2);
                int cl = wn + nj * 8 + 2 * (lane & 3);
                int col = n0 + cl;
                float b0 = col < Q_C ? bias[col] : bias2[col - Q_C];
                float b1 = col + 1 < Q_C ? bias[col + 1] : bias2[col + 1 - Q_C];
                st[rl * FSTRIDE + cl]           = acc[mi][nj][0] + b0;
                st[rl * FSTRIDE + cl + 1]       = acc[mi][nj][1] + b1;
                st[(rl + 8) * FSTRIDE + cl]     = acc[mi][nj][2] + b0;
                st[(rl + 8) * FSTRIDE + cl + 1] = acc[mi][nj][3] + b1;
            }
        __syncthreads();
#pragma unroll
        for (int k = 0; k < 8; k++) {
            int idx = k * 256 + tid;
            int r = idx >> 4, c4 = (idx & 15) * 4;
            float4 v = *(float4*)&st[r * FSTRIDE + c4];
            int m = m0 + r, n = n0 + c4;
            if (n < Q_C) *(float4*)&g_cq_raw[(size_t)m * Q_C + n] = v;
            else *(float4*)&g_ckvkr[(size_t)m * (KV_C + K_ROPE) + n - Q_C] = v;
        }
        return;
    }

    // EPI 3 / 4: half staging with fused scale/rope (EPI 3)
    {
        __half* st = (__half*)smem_raw;   // [128][HSTRIDE]
#pragma unroll
        for (int mi = 0; mi < 2; mi++)
#pragma unroll
            for (int nj = 0; nj < 4; nj++) {
                int rl = wm + mi * 16 + (lane >> 2);
                int cl = wn + nj * 8 + 2 * (lane & 3);
                int col = n0 + cl;
                float b0 = bias[col], b1 = bias[col + 1];
#pragma unroll
                for (int rr = 0; rr < 2; rr++) {
                    float v0 = acc[mi][nj][2 * rr]     + b0;
                    float v1 = acc[mi][nj][2 * rr + 1] + b1;
                    if (EPI == 3) {
                        v0 *= QSC; v1 *= QSC;
                        if (col >= NH * Q_NOPE) {
                            int d = (col - NH * Q_NOPE) % Q_ROPE;  // pair (2i,2i+1)
                            int m = m0 + rl + rr * 8;
                            int b = m / S_LEN, s = m - b * S_LEN;
                            float p = (float)pos[b * S_LEN + s];
                            float inv = __expf(-((float)d / (float)Q_ROPE) * 9.210340371976184f);
                            float sn, cs;
                            __sincosf(p * inv, &sn, &cs);
                            float r0 = v0 * cs - v1 * sn;
                            float r1 = v0 * sn + v1 * cs;
                            v0 = r0; v1 = r1;
                        }
                    }
                    *(__half2*)&st[(rl + rr * 8) * HSTRIDE + cl] = __floats2half2_rn(v0, v1);
                }
            }
        __syncthreads();
#pragma unroll
        for (int k = 0; k < 4; k++) {
            int idx = k * 256 + tid;
            int r = idx >> 3, c8 = (idx & 7) * 8;
            int4 v = *(int4*)&st[r * HSTRIDE + c8];
            int m = m0 + r, n = n0 + c8;
            int b = m / S_LEN, s = m - b * S_LEN;
            if (EPI == 3) {
                int h, d;
                if (n < NH * Q_NOPE) { h = n / Q_NOPE; d = n % Q_NOPE; }
                else { int j = n - NH * Q_NOPE; h = j / Q_ROPE; d = Q_NOPE + (j % Q_ROPE); }
                *(int4*)&g_qs[(((size_t)b * NH + h) * S_LEN + s) * QK_D + d] = v;
            } else {
                if (n < NH * K_NOPE) {
                    int h = n / K_NOPE, d = n % K_NOPE;
                    *(int4*)&g_ks[(((size_t)b * NH + h) * S_LEN + s) * QK_D + d] = v;
                } else {
                    int j = n - NH * K_NOPE;
                    int h = j / V_HD, d = j % V_HD;
                    *(int4*)&g_vs[(((size_t)b * NH + h) * S_LEN + s) * V_HD + d] = v;
                }
            }
        }
    }
}

// ---------------------------------------------------------------------------
// Merged norms: warps 0-3 do q RMSNorm, warps 4-7 do kv RMSNorm + k rope.
// ---------------------------------------------------------------------------
__global__ void norms_k(const float* __restrict__ qw, const float* __restrict__ kvw,
                        const int* __restrict__ pos_ids)
{
    int row = blockIdx.x, t = threadIdx.x;
    __shared__ float s8[8];
    if (t < 128) {
        float v = g_cq_raw[row * Q_C + t];
        float ss = v * v;
#pragma unroll
        for (int off = 16; off > 0; off >>= 1) ss += __shfl_xor_sync(0xffffffffu, ss, off);
        if ((t & 31) == 0) s8[t >> 5] = ss;
        __syncthreads();
        float tot = s8[0] + s8[1] + s8[2] + s8[3];
        float r = rsqrtf(tot * (1.0f / Q_C) + EPSV);
        g_cq_h[row * Q_C + t] = __float2half(qw[t] * v * r);
    } else {
        int tk = t - 128;
        const float* src = &g_ckvkr[row * (KV_C + K_ROPE)];
        float v = src[tk];
        float ss = v * v;
#pragma unroll
        for (int off = 16; off > 0; off >>= 1) ss += __shfl_xor_sync(0xffffffffu, ss, off);
        if ((tk & 31) == 0) s8[4 + (tk >> 5)] = ss;
        __syncthreads();
        float tot = s8[4] + s8[5] + s8[6] + s8[7];
        float r = rsqrtf(tot * (1.0f / KV_C) + EPSV);
        g_ckv_h[row * KV_C + tk] = __float2half(kvw[tk] * v * r);

        if (tk < K_ROPE / 2) {
            int i = tk;
            float xe = src[KV_C + 2 * i];
            float xo = src[KV_C + 2 * i + 1];
            float p = (float)pos_ids[row];
            float inv = expf(-((float)(2 * i) / (float)K_ROPE) * 9.210340371976184f);
            float sn, cs;
            sincosf(p * inv, &sn, &cs);
            __half re = __float2half(xe * cs - xo * sn);
            __half ro = __float2half(xe * sn + xo * cs);
            int b = row / S_LEN, s = row - b * S_LEN;
#pragma unroll
            for (int h = 0; h < NH; h++) {
                size_t base = (((size_t)b * NH + h) * S_LEN + s) * QK_D + K_NOPE;
                g_ks[base + 2 * i]     = re;
                g_ks[base + 2 * i + 1] = ro;
            }
        }
    }
}

// ---------------------------------------------------------------------------
// Flash attention, fp16 mma, base-2 softmax. Grid (32, 8, 2), 128 thr = 4 warps.
// Each warp: 16 query rows x full 256-d output. 64-key chunks.
// Q in REGISTERS (staged once through sK[0]); K AND V double-buffered via
// cp.async, one combined {K,V} commit-group per chunk issued a full chunk
// ahead -> loads overlap compute. Exact rescale-skip on unchanged max.
// ---------------------------------------------------------------------------
#define AQT 64
#define ACH 64
#define KLD 136
#define VLD 264
#define SM_K (2 * ACH * KLD)
#define SM_V (2 * ACH * VLD)
#define SMEM_ATT ((SM_K + SM_V) * 2)   // 102400 bytes

__global__ void __launch_bounds__(128) attn_h_k()
{
    extern __shared__ __half dsm[];
    __half* sK = dsm;                 // [2][ACH][KLD]
    __half* sV = dsm + SM_K;          // [2][ACH][VLD]

    int tid = threadIdx.x, warp = tid >> 5, lane = tid & 31;
    int qt = blockIdx.x, h = blockIdx.y, b = blockIdx.z;

    const __half* Qg = g_qs + (((size_t)b * NH + h) * S_LEN + (size_t)qt * AQT) * QK_D;
    const __half* Kg = g_ks + ((size_t)b * NH + h) * S_LEN * QK_D;
    const __half* Vg = g_vs + ((size_t)b * NH + h) * S_LEN * V_HD;

    u32 sK_a = smem_a(sK), sV_a = smem_a(sV);

    // ---- stage Q through sK[0] (before any cp.async targets it), ldsm to regs
    {
#pragma unroll
        for (int r = 0; r < 8; r++) {
            int idx = r * 128 + tid, row = idx >> 4, c = (idx & 15) * 8;
            *(int4*)&sK[row * KLD + c] = *(const int4*)&Qg[(size_t)row * QK_D + c];
        }
    }
    __syncthreads();
    u32 qa[8][4];
#pragma unroll
    for (int ks = 0; ks < 8; ks++)
        ldsm4(qa[ks], smem_a(&sK[(warp * 16 + (lane & 15)) * KLD + ks * 16 + (lane >> 4) * 8]));
    __syncthreads();   // all warps done reading before prefetch overwrites

    // ---- prologue: {K0,V0} group, {K1,V1} group ----
#pragma unroll
    for (int st = 0; st < 2; st++) {
        const __half* Kn = Kg + (size_t)st * ACH * QK_D;
        const __half* Vn = Vg + (size_t)st * ACH * V_HD;
#pragma unroll
        for (int r = 0; r < 8; r++) {
            int idx = r * 128 + tid, row = idx >> 4, c = (idx & 15) * 8;
            cp_async16(sK_a + ((st * ACH + row) * KLD + c) * 2, &Kn[(size_t)row * QK_D + c]);
        }
#pragma unroll
        for (int r = 0; r < 16; r++) {
            int idx = r * 128 + tid, row = idx >> 5, c = (idx & 31) * 8;
            cp_async16(sV_a + ((st * ACH + row) * VLD + c) * 2, &Vn[(size_t)row * V_HD + c]);
        }
        cp_commit();
    }

    float m_i[2] = { -1e30f, -1e30f }, l_i[2] = { 0.f, 0.f };
    float o[32][4];
#pragma unroll
    for (int nt = 0; nt < 32; nt++)
#pragma unroll
        for (int j = 0; j < 4; j++) o[nt][j] = 0.f;

    const int NCH = S_LEN / ACH;    // 32
    for (int kc = 0; kc < NCH; kc++) {
        int buf = kc & 1;
        cp_wait<1>();          // {K(kc),V(kc)} complete; {K(kc+1),V(kc+1)} may fly
        __syncthreads();

        const __half* sKb = sK + buf * ACH * KLD;
        const __half* sVb = sV + buf * ACH * VLD;

        // ---- scores S = Q K^T (Q pre-scaled by 1/sqrt(d)*log2e) ----
        float sc[8][4];
#pragma unroll
        for (int nj = 0; nj < 8; nj++)
#pragma unroll
            for (int j = 0; j < 4; j++) sc[nj][j] = 0.f;

#pragma unroll
        for (int ks = 0; ks < 8; ks++) {
            u32 bm[8][2];
#pragma unroll
            for (int njp = 0; njp < 4; njp++) {
                u32 r[4];
                ldsm4(r, smem_a(&sKb[(njp * 16 + ((lane >> 4) & 1) * 8 + (lane & 7)) * KLD
                                     + ks * 16 + ((lane >> 3) & 1) * 8]));
                bm[njp * 2][0] = r[0]; bm[njp * 2][1] = r[1];
                bm[njp * 2 + 1][0] = r[2]; bm[njp * 2 + 1][1] = r[3];
            }
#pragma unroll
            for (int nj = 0; nj < 8; nj++) mma16816(sc[nj], qa[ks], bm[nj]);
        }

        // ---- online softmax (base 2), exact rescale-skip ----
        u32 p2[2][8];
#pragma unroll
        for (int i = 0; i < 2; i++) {
            float mx = -1e30f;
#pragma unroll
            for (int nj = 0; nj < 8; nj++)
                mx = fmaxf(mx, fmaxf(sc[nj][2 * i], sc[nj][2 * i + 1]));
            mx = fmaxf(mx, __shfl_xor_sync(0xffffffffu, mx, 1));
            mx = fmaxf(mx, __shfl_xor_sync(0xffffffffu, mx, 2));
            float mn = fmaxf(m_i[i], mx);
            float rs = 0.f;
#pragma unroll
            for (int nj = 0; nj < 8; nj++) {
                float p0 = exp2f(sc[nj][2 * i] - mn);
                float p1 = exp2f(sc[nj][2 * i + 1] - mn);
                rs += p0 + p1;
                __half2 hh = __floats2half2_rn(p0, p1);
                p2[i][nj] = *(u32*)&hh;
            }
            rs += __shfl_xor_sync(0xffffffffu, rs, 1);
            rs += __shfl_xor_sync(0xffffffffu, rs, 2);
            if (mn != m_i[i]) {
                float corr = exp2f(m_i[i] - mn);
                l_i[i] = l_i[i] * corr + rs;
                m_i[i] = mn;
#pragma unroll
                for (int nt = 0; nt < 32; nt++) {
                    o[nt][2 * i] *= corr; o[nt][2 * i + 1] *= corr;
                }
            } else {
                l_i[i] += rs;
            }
        }

        // ---- O += P V ----
#pragma unroll
        for (int kt = 0; kt < 4; kt++) {
            u32 a[4] = { p2[0][2 * kt], p2[1][2 * kt], p2[0][2 * kt + 1], p2[1][2 * kt + 1] };
#pragma unroll
            for (int njp = 0; njp < 16; njp++) {
                u32 r[4];
                ldsm4t(r, smem_a(&sVb[(kt * 16 + ((lane >> 3) & 1) * 8 + (lane & 7)) * VLD
                                      + njp * 16 + (lane >> 4) * 8]));
                u32 b0[2] = { r[0], r[1] }, b1[2] = { r[2], r[3] };
                mma16816(o[njp * 2], a, b0);
                mma16816(o[njp * 2 + 1], a, b1);
            }
        }

        __syncthreads();   // all warps done with sK[buf]/sV[buf]

        // ---- prefetch {K,V}(kc+2) into this buf (one group; empty at tail) ----
        if (kc + 2 < NCH) {
            const __half* Kn = Kg + (size_t)(kc + 2) * ACH * QK_D;
            const __half* Vn = Vg + (size_t)(kc + 2) * ACH * V_HD;
#pragma unroll
            for (int r = 0; r < 8; r++) {
                int idx = r * 128 + tid, row = idx >> 4, c = (idx & 15) * 8;
                cp_async16(sK_a + ((buf * ACH + row) * KLD + c) * 2, &Kn[(size_t)row * QK_D + c]);
            }
#pragma unroll
            for (int r = 0; r < 16; r++) {
                int idx = r * 128 + tid, row = idx >> 5, c = (idx & 31) * 8;
                cp_async16(sV_a + ((buf * ACH + row) * VLD + c) * 2, &Vn[(size_t)row * V_HD + c]);
            }
        }
        cp_commit();   // (possibly empty) keeps group accounting exact
    }

    // ---- epilogue ----
#pragma unroll
    for (int i = 0; i < 2; i++) {
        float inv = 1.f / l_i[i];
        int row = qt * AQT + warp * 16 + (lane >> 2) + i * 8;
        size_t base = ((size_t)b * S_LEN + row) * (NH * V_HD) + h * V_HD;
#pragma unroll
        for (int nt = 0; nt < 32; nt++) {
            __half2 hh = __floats2half2_rn(o[nt][2 * i] * inv, o[nt][2 * i + 1] * inv);
            *(__half2*)&g_attn_h[base + nt * 8 + 2 * (lane & 3)] = hh;
        }
    }
}

// ---------------------------------------------------------------------------
// Launch
// ---------------------------------------------------------------------------
extern "C" void kernel_launch(void* const* d_in, const int* in_sizes, int n_in,
                              void* d_out, int out_size)
{
    const float* x         = (const float*)d_in[0];
    const int*   pos       = (const int*)  d_in[1];
    const float* w_dq_w    = (const float*)d_in[2];
    const float* w_dq_b    = (const float*)d_in[3];
    const float* q_norm_w  = (const float*)d_in[4];
    const float* w_uq_qr_w = (const float*)d_in[5];
    const float* w_uq_qr_b = (const float*)d_in[6];
    const float* w_dkv_w   = (const float*)d_in[7];
    const float* w_dkv_b   = (const float*)d_in[8];
    const float* kv_norm_w = (const float*)d_in[9];
    const float* w_ukv_w   = (const float*)d_in[10];
    const float* w_ukv_b   = (const float*)d_in[11];
    const float* w_o_w     = (const float*)d_in[12];
    const float* w_o_b     = (const float*)d_in[13];
    float* out = (float*)d_out;

    static int smem_set = 0;
    if (!smem_set) {
        cudaFuncSetAttribute(attn_h_k, cudaFuncAttributeMaxDynamicSharedMemorySize, SMEM_ATT);
        smem_set = 1;
    }

    // single merged fp32 -> fp16 conversion (dq/dkv fuse into hw_dqkv)
    cvt_all_k<<<(CN5 + 255) / 256, 256>>>(x, w_dq_w, w_uq_qr_w, w_dkv_w, w_ukv_w, w_o_w);

    // fused dq+dkv down-projection (N=320)
    hgemm_k<1, 0><<<dim3(DQKV_N / HBN, BSROWS / HBM), 256>>>(w_dq_b, w_dkv_b, (float*)0, DQKV_N, DIM, (const int*)0);

    // merged RMSNorms (+ k rope broadcast)
    norms_k<<<BSROWS, 256>>>(q_norm_w, kv_norm_w, pos);

    // up-projections
    hgemm_k<3, 1><<<dim3(NH * QK_D / HBN, BSROWS / HBM), 256>>>(w_uq_qr_b, (const float*)0, (float*)0, NH * QK_D, Q_C, pos);
    hgemm_k<4, 2><<<dim3(NH * (K_NOPE + V_HD) / HBN, BSROWS / HBM), 256>>>(w_ukv_b, (const float*)0, (float*)0, NH * (K_NOPE + V_HD), KV_C, (const int*)0);

    // attention
    attn_h_k<<<dim3(S_LEN / AQT, NH, BATCH), 128, SMEM_ATT>>>();

    // output projection
    hgemm_k<0, 3><<<dim3(DIM / HBN, BSROWS / HBM), 256>>>(w_o_b, (const float*)0, out, DIM, NH * V_HD, (const int*)0);
}